// round 3
// baseline (speedup 1.0000x reference)
#include <cuda_runtime.h>
#include <cstdint>

#define N_USERS 100000
#define M_ITEMS 200000
#define N_NODES 300000
#define N_EDGES 1200000
#define BATCH   4096

// ---------------- scratch (device globals: allocation-free rule) -------------
__device__ float4 g_ego4 [N_NODES * 16];
__device__ float4 g_side4[N_NODES * 16];
__device__ float4 g_acc4 [N_NODES * 16];

// ---------------- asm helpers -------------------------------------------------
__device__ __forceinline__ uint64_t lds64(uint32_t a) {
    uint64_t v; asm volatile("ld.shared.b64 %0, [%1];" : "=l"(v) : "r"(a)); return v;
}
__device__ __forceinline__ void lds128(uint64_t& x, uint64_t& y, uint32_t a) {
    asm volatile("ld.shared.v2.u64 {%0,%1}, [%2];" : "=l"(x), "=l"(y) : "r"(a));
}
__device__ __forceinline__ uint64_t fma2(uint64_t a, uint64_t b, uint64_t c) {
    uint64_t d; asm("fma.rn.f32x2 %0, %1, %2, %3;" : "=l"(d) : "l"(a), "l"(b), "l"(c)); return d;
}
__device__ __forceinline__ uint64_t packf2(float lo, float hi) {
    uint64_t p; asm("mov.b64 %0, {%1,%2};" : "=l"(p) : "f"(lo), "f"(hi)); return p;
}
__device__ __forceinline__ void unpackf2(float& lo, float& hi, uint64_t p) {
    asm("mov.b64 {%0,%1}, %2;" : "=f"(lo), "=f"(hi) : "l"(p));
}
__device__ __forceinline__ uint32_t s2u(const void* p) {
    return (uint32_t)__cvta_generic_to_shared(p);
}

// ---------------- init: ego = acc = concat(user,item); side = 0 --------------
__global__ __launch_bounds__(256) void init_kernel(const float4* __restrict__ ue,
                                                   const float4* __restrict__ ie) {
    int i = blockIdx.x * 256 + threadIdx.x;
    if (i >= N_NODES * 16) return;
    float4 v = (i < N_USERS * 16) ? ue[i] : ie[i - N_USERS * 16];
    g_ego4[i] = v;
    g_acc4[i] = v;
    g_side4[i] = make_float4(0.f, 0.f, 0.f, 0.f);
}

// ---------------- spmm: side[r] += vals[e] * ego[cols[e]] --------------------
__global__ __launch_bounds__(256) void spmm_kernel(const int*   __restrict__ rows,
                                                   const int*   __restrict__ cols,
                                                   const float* __restrict__ vals) {
    int gid = blockIdx.x * 256 + threadIdx.x;
    int e = gid >> 4;
    if (e >= N_EDGES) return;
    int q = gid & 15;
    int r = __ldg(rows + e);
    int c = __ldg(cols + e);
    float v = __ldg(vals + e);
    float4 x = g_ego4[c * 16 + q];
    float* p = (float*)g_side4 + ((size_t)r * 64 + q * 4);
    asm volatile("red.global.add.v4.f32 [%0], {%1,%2,%3,%4};"
                 :: "l"(p), "f"(v * x.x), "f"(v * x.y), "f"(v * x.z), "f"(v * x.w)
                 : "memory");
}

// ---------------- transform ---------------------------------------------------
// y = LReLU(side@Wgc + (ego*side)@Wbi + bgc + bbi); row-normalize; ego=y; acc+=y
// R1 structure (dup'd float2 operands in smem) at TTILE=64 -> 97KB smem,
// 2 CTAs/SM, 16 warps. Thread tile = 2 rows x 8 cols.
#define TTILE     64
#define SS_STRIDE 65                        // float2 per row (pad kills conflicts)
#define SS_BYTES  (TTILE * SS_STRIDE * 8)   // 33280
#define SMEM_TR   (2 * SS_BYTES + 2 * 64 * 64 * 4)  // 99328

__global__ __launch_bounds__(256, 2) void transform_kernel(const float* __restrict__ Wgc,
                                                           const float* __restrict__ bgc,
                                                           const float* __restrict__ Wbi,
                                                           const float* __restrict__ bbi,
                                                           int zero_side) {
    extern __shared__ unsigned char smem[];
    float2* sS  = (float2*)smem;                       // dup side  [64][65]
    float2* sU  = (float2*)(smem + SS_BYTES);          // dup ego*side
    float*  sWg = (float*)(smem + 2 * SS_BYTES);       // [64][64]
    float*  sWb = sWg + 64 * 64;

    const float* side = (const float*)g_side4;
    const float* ego  = (const float*)g_ego4;
    float*       sdw  = (float*)g_side4;

    int tid  = threadIdx.x;
    int base = blockIdx.x * TTILE;

    // --- load tiles (coalesced gmem loads, conflict-free dup stores) ---
    #pragma unroll
    for (int it = 0; it < 4; ++it) {
        int idx = it * 256 + tid;            // 0..1023
        int lr  = idx >> 4;                  // row 0..63
        int q   = idx & 15;                  // lane-k 0..15
        int n   = base + lr;
        float sv[4] = {0.f, 0.f, 0.f, 0.f};
        float ev[4] = {0.f, 0.f, 0.f, 0.f};
        if (n < N_NODES) {
            size_t o = (size_t)n * 64 + q;
            #pragma unroll
            for (int c = 0; c < 4; ++c) {
                sv[c] = side[o + 16 * c];
                ev[c] = ego [o + 16 * c];
                if (zero_side) sdw[o + 16 * c] = 0.f;
            }
        }
        float2* ps = sS + lr * SS_STRIDE;
        float2* pu = sU + lr * SS_STRIDE;
        #pragma unroll
        for (int c = 0; c < 4; ++c) {
            ps[q + 16 * c] = make_float2(sv[c], sv[c]);
            float u = ev[c] * sv[c];
            pu[q + 16 * c] = make_float2(u, u);
        }
    }
    for (int i = tid; i < 4096; i += 256) { sWg[i] = Wgc[i]; sWb[i] = Wbi[i]; }
    __syncthreads();

    // --- register-tiled GEMM: thread = 2 rows x 8 cols, f32x2 over col pairs
    int cq = tid & 7;     // cols 8*cq .. 8*cq+7
    int rq = tid >> 3;    // rows 2*rq .. 2*rq+1

    uint32_t aS  = s2u(sS + (2 * rq) * SS_STRIDE);
    uint32_t aU  = s2u(sU + (2 * rq) * SS_STRIDE);
    uint32_t aWg = s2u(sWg + 8 * cq);
    uint32_t aWb = s2u(sWb + 8 * cq);

    uint64_t acc[2][4];
    #pragma unroll
    for (int cp = 0; cp < 4; ++cp) {
        int c0 = 8 * cq + 2 * cp;
        uint64_t p = packf2(bgc[c0] + bbi[c0], bgc[c0 + 1] + bbi[c0 + 1]);
        acc[0][cp] = p; acc[1][cp] = p;
    }

    #pragma unroll 8
    for (int j = 0; j < 64; ++j) {
        uint64_t sv[2], uv[2], wg[4], wb[4];
        #pragma unroll
        for (int r = 0; r < 2; ++r) {
            sv[r] = lds64(aS + j * 8 + r * (SS_STRIDE * 8));
            uv[r] = lds64(aU + j * 8 + r * (SS_STRIDE * 8));
        }
        lds128(wg[0], wg[1], aWg + j * 256);
        lds128(wg[2], wg[3], aWg + j * 256 + 16);
        lds128(wb[0], wb[1], aWb + j * 256);
        lds128(wb[2], wb[3], aWb + j * 256 + 16);
        #pragma unroll
        for (int r = 0; r < 2; ++r)
            #pragma unroll
            for (int cp = 0; cp < 4; ++cp)
                acc[r][cp] = fma2(uv[r], wb[cp], fma2(sv[r], wg[cp], acc[r][cp]));
    }

    // --- leaky relu into shared, then row-norm + store ---
    __syncthreads();
    float* sY = (float*)smem;  // [64][64], reuses sS/sU region
    #pragma unroll
    for (int r = 0; r < 2; ++r) {
        #pragma unroll
        for (int cp = 0; cp < 4; ++cp) {
            float lo, hi;
            unpackf2(lo, hi, acc[r][cp]);
            lo = lo > 0.f ? lo : 0.2f * lo;
            hi = hi > 0.f ? hi : 0.2f * hi;
            int row = 2 * rq + r, col = 8 * cq + 2 * cp;
            sY[row * 64 + col]     = lo;
            sY[row * 64 + col + 1] = hi;
        }
    }
    __syncthreads();

    int lane = tid & 31, warp = tid >> 5;
    float* ego_w = (float*)g_ego4;
    float* acc_w = (float*)g_acc4;
    #pragma unroll
    for (int r = warp; r < TTILE; r += 8) {
        float v1 = sY[r * 64 + lane];
        float v2 = sY[r * 64 + 32 + lane];
        float ss = v1 * v1 + v2 * v2;
        #pragma unroll
        for (int o = 16; o > 0; o >>= 1) ss += __shfl_xor_sync(0xffffffffu, ss, o);
        float sc = 1.0f / fmaxf(sqrtf(ss), 1e-12f);
        v1 *= sc; v2 *= sc;
        int n = base + r;
        if (n < N_NODES) {
            size_t o = (size_t)n * 64 + lane;
            ego_w[o]      = v1;
            ego_w[o + 32] = v2;
            acc_w[o]      += v1;
            acc_w[o + 32] += v2;
        }
    }
}

// ---------------- output: dot(acc_u, acc_i)/16 --------------------------------
__global__ __launch_bounds__(256) void out_kernel(const int* __restrict__ users,
                                                  const int* __restrict__ items,
                                                  float* __restrict__ out) {
    int b = blockIdx.x * 8 + (threadIdx.x >> 5);
    int lane = threadIdx.x & 31;
    if (b >= BATCH) return;
    int u = __ldg(users + b);
    int i = __ldg(items + b);
    const float* pu = (const float*)g_acc4 + (size_t)u * 64;
    const float* pi = (const float*)g_acc4 + (size_t)(N_USERS + i) * 64;
    float s = pu[lane] * pi[lane] + pu[lane + 32] * pi[lane + 32];
    #pragma unroll
    for (int o = 16; o > 0; o >>= 1) s += __shfl_xor_sync(0xffffffffu, s, o);
    if (lane == 0) out[b] = s * (1.0f / 16.0f);
}

// ---------------- host launcher ------------------------------------------------
extern "C" void kernel_launch(void* const* d_in, const int* in_sizes, int n_in,
                              void* d_out, int out_size) {
    const int*   users    = (const int*)  d_in[0];
    const int*   items    = (const int*)  d_in[1];
    const int*   rows     = (const int*)  d_in[2];
    const int*   cols     = (const int*)  d_in[3];
    const float* vals     = (const float*)d_in[4];
    const float* user_emb = (const float*)d_in[5];
    const float* item_emb = (const float*)d_in[6];
    const float* W_gc     = (const float*)d_in[7];
    const float* b_gc     = (const float*)d_in[8];
    const float* W_bi     = (const float*)d_in[9];
    const float* b_bi     = (const float*)d_in[10];
    float*       out      = (float*)d_out;

    cudaFuncSetAttribute(transform_kernel,
                         cudaFuncAttributeMaxDynamicSharedMemorySize, SMEM_TR);

    const int nvec = N_NODES * 16;
    init_kernel<<<(nvec + 255) / 256, 256>>>((const float4*)user_emb,
                                             (const float4*)item_emb);

    for (int k = 0; k < 3; ++k) {
        spmm_kernel<<<(N_EDGES * 16) / 256, 256>>>(rows, cols, vals);
        transform_kernel<<<(N_NODES + TTILE - 1) / TTILE, 256, SMEM_TR>>>(
            W_gc + k * 64 * 64, b_gc + k * 64,
            W_bi + k * 64 * 64, b_bi + k * 64,
            (k < 2) ? 1 : 0);
    }

    out_kernel<<<BATCH / 8, 256>>>(users, items, out);
}

// round 5
// speedup vs baseline: 4.2728x; 4.2728x over previous
#include <cuda_runtime.h>
#include <cuda_bf16.h>
#include <cstdint>

#define N_USERS 100000
#define M_ITEMS 200000
#define N_NODES 300000
#define N_EDGES 1200000
#define BATCH   4096

// ---------------- scratch (device globals: allocation-free rule) -------------
__device__ float4 g_ego4 [N_NODES * 16];
__device__ float4 g_side4[N_NODES * 16];
__device__ float4 g_acc4 [N_NODES * 16];

// ---------------- helpers ------------------------------------------------------
__device__ __forceinline__ uint32_t s2u(const void* p) {
    return (uint32_t)__cvta_generic_to_shared(p);
}
__device__ __forceinline__ void ldsm4(uint32_t* r, uint32_t a) {
    asm volatile("ldmatrix.sync.aligned.m8n8.x4.shared.b16 {%0,%1,%2,%3}, [%4];"
                 : "=r"(r[0]), "=r"(r[1]), "=r"(r[2]), "=r"(r[3]) : "r"(a));
}
__device__ __forceinline__ void ldsm2(uint32_t* r, uint32_t a) {
    asm volatile("ldmatrix.sync.aligned.m8n8.x2.shared.b16 {%0,%1}, [%2];"
                 : "=r"(r[0]), "=r"(r[1]) : "r"(a));
}
__device__ __forceinline__ void mma_bf16(float* c, const uint32_t* a, const uint32_t* b) {
    asm volatile("mma.sync.aligned.m16n8k16.row.col.f32.bf16.bf16.f32 "
                 "{%0,%1,%2,%3}, {%4,%5,%6,%7}, {%8,%9}, {%0,%1,%2,%3};"
                 : "+f"(c[0]), "+f"(c[1]), "+f"(c[2]), "+f"(c[3])
                 : "r"(a[0]), "r"(a[1]), "r"(a[2]), "r"(a[3]), "r"(b[0]), "r"(b[1]));
}
// hi/lo bf16 split of a float pair -> packed bf16x2 words
__device__ __forceinline__ void split2(float a, float b, uint32_t& hi, uint32_t& lo) {
    __nv_bfloat162 h = __floats2bfloat162_rn(a, b);
    float ra = a - __bfloat162float(h.x);
    float rb = b - __bfloat162float(h.y);
    __nv_bfloat162 l = __floats2bfloat162_rn(ra, rb);
    hi = *reinterpret_cast<uint32_t*>(&h);
    lo = *reinterpret_cast<uint32_t*>(&l);
}

// ---------------- init / zero / spmm / out: exact R1-proven versions ----------
__global__ __launch_bounds__(256) void init_kernel(const float4* __restrict__ ue,
                                                   const float4* __restrict__ ie) {
    int i = blockIdx.x * 256 + threadIdx.x;
    if (i >= N_NODES * 16) return;
    float4 v = (i < N_USERS * 16) ? ue[i] : ie[i - N_USERS * 16];
    g_ego4[i] = v;
    g_acc4[i] = v;
}

__global__ __launch_bounds__(256) void zero_side_kernel() {
    int i = blockIdx.x * 256 + threadIdx.x;
    if (i < N_NODES * 16) g_side4[i] = make_float4(0.f, 0.f, 0.f, 0.f);
}

__global__ __launch_bounds__(256) void spmm_kernel(const int*   __restrict__ rows,
                                                   const int*   __restrict__ cols,
                                                   const float* __restrict__ vals) {
    int gid = blockIdx.x * 256 + threadIdx.x;
    int e = gid >> 4;
    if (e >= N_EDGES) return;
    int q = gid & 15;
    int r = __ldg(rows + e);
    int c = __ldg(cols + e);
    float v = __ldg(vals + e);
    float4 x = g_ego4[c * 16 + q];
    float* p = (float*)g_side4 + ((size_t)r * 64 + q * 4);
    asm volatile("red.global.add.v4.f32 [%0], {%1,%2,%3,%4};"
                 :: "l"(p), "f"(v * x.x), "f"(v * x.y), "f"(v * x.z), "f"(v * x.w)
                 : "memory");
}

// ---------------- transform via mma.sync bf16-split GEMM ----------------------
// A = [S | E*S] (128 rows x 128 k), B = [Wgc; Wbi]^T stored as Wt[n][k].
// y = LReLU(A @ B + b); row-normalize; ego = y; acc += y.
#define TTILE   128
#define ASTRIDE 272                         // bytes per A/W row (136 bf16, pad)
#define SM_BS   0
#define SM_AH   256
#define SM_AL   (SM_AH + 128 * ASTRIDE)     // 35072
#define SM_WH   (SM_AL + 128 * ASTRIDE)     // 69888
#define SM_WL   (SM_WH + 64 * ASTRIDE)      // 87296
#define SMEM_TR (SM_WL + 64 * ASTRIDE)      // 104704

__global__ __launch_bounds__(256) void transform_kernel(const float* __restrict__ Wgc,
                                                        const float* __restrict__ bgc,
                                                        const float* __restrict__ Wbi,
                                                        const float* __restrict__ bbi) {
    extern __shared__ unsigned char smem[];
    int tid  = threadIdx.x;
    int wid  = tid >> 5;
    int lane = tid & 31;
    int base = blockIdx.x * TTILE;

    // ---- bias sum ----
    if (tid < 64) ((float*)(smem + SM_BS))[tid] = bgc[tid] + bbi[tid];

    // ---- stage A (hi/lo split): thread = (row, half-of-K) ----
    {
        int row  = tid >> 1;
        int half = tid & 1;                  // 0: k 0..63 = S; 1: k 64..127 = E*S
        int n    = base + row;
        const float4* sp = g_side4 + (size_t)n * 16;
        const float4* ep = g_ego4  + (size_t)n * 16;
        unsigned char* ah = smem + SM_AH + row * ASTRIDE + half * 128;
        unsigned char* al = smem + SM_AL + row * ASTRIDE + half * 128;
        #pragma unroll
        for (int g = 0; g < 4; ++g) {        // 16 k per chunk
            float x[16];
            if (n < N_NODES) {
                #pragma unroll
                for (int j = 0; j < 4; ++j) {
                    float4 v = sp[g * 4 + j];
                    x[4*j] = v.x; x[4*j+1] = v.y; x[4*j+2] = v.z; x[4*j+3] = v.w;
                }
                if (half) {
                    #pragma unroll
                    for (int j = 0; j < 4; ++j) {
                        float4 e = ep[g * 4 + j];
                        x[4*j] *= e.x; x[4*j+1] *= e.y; x[4*j+2] *= e.z; x[4*j+3] *= e.w;
                    }
                }
            } else {
                #pragma unroll
                for (int j = 0; j < 16; ++j) x[j] = 0.f;
            }
            uint32_t hv[8], lv[8];
            #pragma unroll
            for (int p = 0; p < 8; ++p) split2(x[2*p], x[2*p+1], hv[p], lv[p]);
            *(uint4*)(ah + g * 32)      = make_uint4(hv[0], hv[1], hv[2], hv[3]);
            *(uint4*)(ah + g * 32 + 16) = make_uint4(hv[4], hv[5], hv[6], hv[7]);
            *(uint4*)(al + g * 32)      = make_uint4(lv[0], lv[1], lv[2], lv[3]);
            *(uint4*)(al + g * 32 + 16) = make_uint4(lv[4], lv[5], lv[6], lv[7]);
        }
    }

    // ---- stage W^T (hi/lo split): Wt[n][k], k = [Wgc rows; Wbi rows] ----
    {
        int n  = tid & 63;
        int kq = tid >> 6;                   // k base = 32*kq
        int ks = kq * 32;
        unsigned char* wh = smem + SM_WH + n * ASTRIDE + ks * 2;
        unsigned char* wl = smem + SM_WL + n * ASTRIDE + ks * 2;
        #pragma unroll
        for (int g = 0; g < 4; ++g) {        // 8 k per chunk
            uint32_t hv[4], lv[4];
            #pragma unroll
            for (int p = 0; p < 4; ++p) {
                int k = ks + g * 8 + 2 * p;
                float v0 = (k < 64)     ? __ldg(Wgc + (size_t)k * 64 + n)
                                        : __ldg(Wbi + (size_t)(k - 64) * 64 + n);
                float v1 = (k + 1 < 64) ? __ldg(Wgc + (size_t)(k + 1) * 64 + n)
                                        : __ldg(Wbi + (size_t)(k + 1 - 64) * 64 + n);
                split2(v0, v1, hv[p], lv[p]);
            }
            *(uint4*)(wh + g * 16) = make_uint4(hv[0], hv[1], hv[2], hv[3]);
            *(uint4*)(wl + g * 16) = make_uint4(lv[0], lv[1], lv[2], lv[3]);
        }
    }
    __syncthreads();

    // ---- HMMA mainloop: warp = 16 rows x 64 cols ----
    int m0 = wid * 16;
    uint32_t aAh = s2u(smem + SM_AH) + (m0 + (lane & 15)) * ASTRIDE + ((lane >> 4) * 8) * 2;
    uint32_t aAl = aAh + (SM_AL - SM_AH);
    uint32_t aBh = s2u(smem + SM_WH) + (lane & 7) * ASTRIDE + (((lane >> 3) & 1) * 8) * 2;
    uint32_t aBl = aBh + (SM_WL - SM_WH);

    float acc[8][4];
    #pragma unroll
    for (int nt = 0; nt < 8; ++nt)
        #pragma unroll
        for (int j = 0; j < 4; ++j) acc[nt][j] = 0.f;

    #pragma unroll
    for (int kk = 0; kk < 8; ++kk) {
        uint32_t ah[4], al[4];
        ldsm4(ah, aAh + kk * 32);
        ldsm4(al, aAl + kk * 32);
        #pragma unroll
        for (int nt = 0; nt < 8; ++nt) {
            uint32_t bh[2], bl[2];
            ldsm2(bh, aBh + nt * (8 * ASTRIDE) + kk * 32);
            ldsm2(bl, aBl + nt * (8 * ASTRIDE) + kk * 32);
            mma_bf16(acc[nt], ah, bh);   // hi*hi
            mma_bf16(acc[nt], ah, bl);   // hi*lo
            mma_bf16(acc[nt], al, bh);   // lo*hi
        }
    }

    // ---- epilogue in-fragment: bias + LReLU + row-norm, write ego/acc ----
    const float* bs = (const float*)(smem + SM_BS);
    int q  = lane & 3;                       // col pair selector
    int gr = lane >> 2;                      // row-in-group
    float ss0 = 0.f, ss1 = 0.f;
    #pragma unroll
    for (int nt = 0; nt < 8; ++nt) {
        float b0 = bs[nt * 8 + 2 * q], b1 = bs[nt * 8 + 2 * q + 1];
        float c0 = acc[nt][0] + b0, c1 = acc[nt][1] + b1;
        float c2 = acc[nt][2] + b0, c3 = acc[nt][3] + b1;
        c0 = c0 > 0.f ? c0 : 0.2f * c0;
        c1 = c1 > 0.f ? c1 : 0.2f * c1;
        c2 = c2 > 0.f ? c2 : 0.2f * c2;
        c3 = c3 > 0.f ? c3 : 0.2f * c3;
        ss0 += c0 * c0 + c1 * c1;
        ss1 += c2 * c2 + c3 * c3;
        acc[nt][0] = c0; acc[nt][1] = c1; acc[nt][2] = c2; acc[nt][3] = c3;
    }
    // lanes sharing a row differ only in bits 0-1
    ss0 += __shfl_xor_sync(0xffffffffu, ss0, 1);
    ss0 += __shfl_xor_sync(0xffffffffu, ss0, 2);
    ss1 += __shfl_xor_sync(0xffffffffu, ss1, 1);
    ss1 += __shfl_xor_sync(0xffffffffu, ss1, 2);
    float sc0 = 1.0f / fmaxf(sqrtf(ss0), 1e-12f);
    float sc1 = 1.0f / fmaxf(sqrtf(ss1), 1e-12f);

    int n0 = base + m0 + gr;
    int n1 = n0 + 8;
    float* ego_w = (float*)g_ego4;
    float* acc_w = (float*)g_acc4;
    #pragma unroll
    for (int nt = 0; nt < 8; ++nt) {
        int col = nt * 8 + 2 * q;
        if (n0 < N_NODES) {
            size_t o = (size_t)n0 * 64 + col;
            float2 v = make_float2(acc[nt][0] * sc0, acc[nt][1] * sc0);
            *(float2*)(ego_w + o) = v;
            float2 a = *(float2*)(acc_w + o);
            a.x += v.x; a.y += v.y;
            *(float2*)(acc_w + o) = a;
        }
        if (n1 < N_NODES) {
            size_t o = (size_t)n1 * 64 + col;
            float2 v = make_float2(acc[nt][2] * sc1, acc[nt][3] * sc1);
            *(float2*)(ego_w + o) = v;
            float2 a = *(float2*)(acc_w + o);
            a.x += v.x; a.y += v.y;
            *(float2*)(acc_w + o) = a;
        }
    }
}

// ---------------- output: dot(acc_u, acc_i)/16 --------------------------------
__global__ __launch_bounds__(256) void out_kernel(const int* __restrict__ users,
                                                  const int* __restrict__ items,
                                                  float* __restrict__ out) {
    int b = blockIdx.x * 8 + (threadIdx.x >> 5);
    int lane = threadIdx.x & 31;
    if (b >= BATCH) return;
    int u = __ldg(users + b);
    int i = __ldg(items + b);
    const float* pu = (const float*)g_acc4 + (size_t)u * 64;
    const float* pi = (const float*)g_acc4 + (size_t)(N_USERS + i) * 64;
    float s = pu[lane] * pi[lane] + pu[lane + 32] * pi[lane + 32];
    #pragma unroll
    for (int o = 16; o > 0; o >>= 1) s += __shfl_xor_sync(0xffffffffu, s, o);
    if (lane == 0) out[b] = s * (1.0f / 16.0f);
}

// ---------------- host launcher ------------------------------------------------
extern "C" void kernel_launch(void* const* d_in, const int* in_sizes, int n_in,
                              void* d_out, int out_size) {
    const int*   users    = (const int*)  d_in[0];
    const int*   items    = (const int*)  d_in[1];
    const int*   rows     = (const int*)  d_in[2];
    const int*   cols     = (const int*)  d_in[3];
    const float* vals     = (const float*)d_in[4];
    const float* user_emb = (const float*)d_in[5];
    const float* item_emb = (const float*)d_in[6];
    const float* W_gc     = (const float*)d_in[7];
    const float* b_gc     = (const float*)d_in[8];
    const float* W_bi     = (const float*)d_in[9];
    const float* b_bi     = (const float*)d_in[10];
    float*       out      = (float*)d_out;

    cudaFuncSetAttribute(transform_kernel,
                         cudaFuncAttributeMaxDynamicSharedMemorySize, SMEM_TR);

    const int nvec = N_NODES * 16;
    init_kernel<<<(nvec + 255) / 256, 256>>>((const float4*)user_emb,
                                             (const float4*)item_emb);

    for (int k = 0; k < 3; ++k) {
        zero_side_kernel<<<(nvec + 255) / 256, 256>>>();
        spmm_kernel<<<(N_EDGES * 16) / 256, 256>>>(rows, cols, vals);
        transform_kernel<<<(N_NODES + TTILE - 1) / TTILE, 256, SMEM_TR>>>(
            W_gc + k * 64 * 64, b_gc + k * 64,
            W_bi + k * 64 * 64, b_bi + k * 64);
    }

    out_kernel<<<BATCH / 8, 256>>>(users, items, out);
}